// round 1
// baseline (speedup 1.0000x reference)
#include <cuda_runtime.h>
#include <math.h>

// ---------------------------------------------------------------------------
// Performer FAVOR+ cross-attention forward, fp32 baseline.
// B=8, Nq=1024, Nk=4096, D=512, H=8, DH=64, M=256
// ---------------------------------------------------------------------------

#define BATCH 8
#define NQ 1024
#define NK 4096
#define DMODEL 512
#define NH 8
#define DHD 64
#define MF 256
#define BHN 64          // BATCH * NH

#define DN_SCALE 0.35355339059327379f  // 64^-0.25
#define RATIO 0.0625f                  // 256^-0.5
#define EPSF 1e-4f

// -------------------- scratch (static device allocations) ------------------
__device__ float g_Q[BATCH * NQ * DMODEL];          // 16 MB
__device__ float g_K[BATCH * NK * DMODEL];          // 64 MB
__device__ float g_V[BATCH * NK * DMODEL];          // 64 MB
__device__ float g_projT[DHD * MF];                 // proj transposed [64][256]
__device__ float g_qp[BHN * NQ * MF];               // dashQ -> qp, 64 MB
__device__ float g_kp[(size_t)BHN * NK * MF];       // dashK -> kp, 256 MB
__device__ float g_maxPart[BHN * 16];
__device__ float g_stabK[BHN];
__device__ float g_kcPart[4 * BHN * MF];
__device__ float g_kc[BHN * MF];
__device__ float g_ctxPart[4 * BHN * MF * DHD];     // 16 MB
__device__ float g_ctx[BHN * MF * DHD];             // 4 MB
__device__ float g_tmp[BHN * NQ * DHD];             // 16 MB
__device__ float g_attn[BATCH * NQ * DMODEL];       // 16 MB

// -------------------- block reduction helpers (256 threads) ----------------
__device__ __forceinline__ float warpRedSum(float v) {
#pragma unroll
    for (int o = 16; o > 0; o >>= 1) v += __shfl_xor_sync(0xffffffffu, v, o);
    return v;
}
__device__ __forceinline__ float warpRedMax(float v) {
#pragma unroll
    for (int o = 16; o > 0; o >>= 1) v = fmaxf(v, __shfl_xor_sync(0xffffffffu, v, o));
    return v;
}
__device__ __forceinline__ float blockSum256(float v) {
    __shared__ float sh[8];
    v = warpRedSum(v);
    int lane = threadIdx.x & 31, w = threadIdx.x >> 5;
    if (lane == 0) sh[w] = v;
    __syncthreads();
    float s = sh[0];
#pragma unroll
    for (int i = 1; i < 8; i++) s += sh[i];
    return s;
}
__device__ __forceinline__ float blockMax256(float v) {
    __shared__ float sh[8];
    v = warpRedMax(v);
    int lane = threadIdx.x & 31, w = threadIdx.x >> 5;
    if (lane == 0) sh[w] = v;
    __syncthreads();
    float m = sh[0];
#pragma unroll
    for (int i = 1; i < 8; i++) m = fmaxf(m, sh[i]);
    return m;
}

// -------------------- generic SGEMM (NN), 128x128x8, 256 thr, 8x8/thr ------
// C = alpha * A[M,K] @ B[K,N] (+ bias), row-major, batched over grid.z:
//   off = (z / Hd) * off*b + (z % Hd) * off*h
// Requirements: M % 128 == 0, K % 8 == 0, N % 4 == 0 (N may be < 128, guarded).
__global__ __launch_bounds__(256) void sgemm_nn(
    const float* __restrict__ A, const float* __restrict__ B,
    float* __restrict__ C, const float* __restrict__ bias,
    int M, int N, int K, int lda, int ldb, int ldc,
    int Hd, long offAb, long offAh, long offBb, long offBh,
    long offCb, long offCh, float alpha)
{
    int z = blockIdx.z;
    int zb = z / Hd, zh = z % Hd;
    A += (long)zb * offAb + (long)zh * offAh;
    B += (long)zb * offBb + (long)zh * offBh;
    C += (long)zb * offCb + (long)zh * offCh;

    __shared__ float As[8][128];
    __shared__ float Bs[8][128];

    int tid = threadIdx.x;
    int m0 = blockIdx.y * 128;
    int n0 = blockIdx.x * 128;

    int arow = tid >> 1;             // 0..127
    int ak = (tid & 1) * 4;          // 0 or 4
    int brow = tid >> 5;             // 0..7
    int bcol = (tid & 31) * 4;       // 0..124

    int tx = tid & 15;               // n dir
    int ty = tid >> 4;               // m dir

    float acc[8][8];
#pragma unroll
    for (int i = 0; i < 8; i++)
#pragma unroll
        for (int j = 0; j < 8; j++) acc[i][j] = 0.f;

    for (int k0 = 0; k0 < K; k0 += 8) {
        float4 av = *(const float4*)(A + (long)(m0 + arow) * lda + k0 + ak);
        float4 bv = make_float4(0.f, 0.f, 0.f, 0.f);
        if (n0 + bcol < N)
            bv = *(const float4*)(B + (long)(k0 + brow) * ldb + n0 + bcol);
        __syncthreads();
        As[ak + 0][arow] = av.x;
        As[ak + 1][arow] = av.y;
        As[ak + 2][arow] = av.z;
        As[ak + 3][arow] = av.w;
        *(float4*)&Bs[brow][bcol] = bv;
        __syncthreads();
#pragma unroll
        for (int kk = 0; kk < 8; kk++) {
            float a[8], b[8];
            *(float4*)(a)     = *(const float4*)&As[kk][ty * 8];
            *(float4*)(a + 4) = *(const float4*)&As[kk][ty * 8 + 4];
            *(float4*)(b)     = *(const float4*)&Bs[kk][tx * 8];
            *(float4*)(b + 4) = *(const float4*)&Bs[kk][tx * 8 + 4];
#pragma unroll
            for (int i = 0; i < 8; i++)
#pragma unroll
                for (int j = 0; j < 8; j++)
                    acc[i][j] = fmaf(a[i], b[j], acc[i][j]);
        }
    }
    __syncthreads();

#pragma unroll
    for (int i = 0; i < 8; i++) {
        int m = m0 + ty * 8 + i;
#pragma unroll
        for (int j = 0; j < 8; j += 4) {
            int n = n0 + tx * 8 + j;
            if (n < N) {
                float4 v;
                v.x = alpha * acc[i][j + 0];
                v.y = alpha * acc[i][j + 1];
                v.z = alpha * acc[i][j + 2];
                v.w = alpha * acc[i][j + 3];
                if (bias) {
                    v.x += bias[n]; v.y += bias[n + 1];
                    v.z += bias[n + 2]; v.w += bias[n + 3];
                }
                *(float4*)(C + (long)m * ldc + n) = v;
            }
        }
    }
}

// -------------------- ctx = kp^T @ V (TN GEMM, hardcoded) -------------------
// Per (b,h): ctx[m,d] = sum_s kp[s,m] * V[s,d].  kp stored [s,256] (== [K,M]).
// grid: x = m-block (2), z = split*64 + bh. Split-K=4 (1024 rows each).
__global__ __launch_bounds__(256) void ctx_tn(
    const float* __restrict__ KP, const float* __restrict__ V,
    float* __restrict__ Cp)
{
    int z = blockIdx.z;
    int split = z >> 6, bh = z & 63;
    int b = bh >> 3, h = bh & 7;
    const float* A = KP + (long)bh * NK * MF + (long)split * 1024 * MF; // [1024,256]
    const float* B = V + ((long)b * NK + split * 1024) * DMODEL + h * DHD;
    float* C = Cp + ((long)split * BHN + bh) * MF * DHD;
    int m0 = blockIdx.x * 128;

    __shared__ float As[16][128];
    __shared__ float Bs[16][64];
    int tid = threadIdx.x;
    int tx = tid & 15;   // n: 4 each
    int ty = tid >> 4;   // m: 8 each

    float acc[8][4];
#pragma unroll
    for (int i = 0; i < 8; i++)
#pragma unroll
        for (int j = 0; j < 4; j++) acc[i][j] = 0.f;

    int ka0 = tid >> 5, ma0 = (tid & 31) * 4;            // A pieces
    int ka1 = (tid + 256) >> 5;                          // = ka0 + 8
    int kb = tid >> 4, nb = (tid & 15) * 4;              // B piece

    for (int k0 = 0; k0 < 1024; k0 += 16) {
        float4 a0 = *(const float4*)(A + (long)(k0 + ka0) * MF + m0 + ma0);
        float4 a1 = *(const float4*)(A + (long)(k0 + ka1) * MF + m0 + ma0);
        float4 b0 = *(const float4*)(B + (long)(k0 + kb) * DMODEL + nb);
        __syncthreads();
        *(float4*)&As[ka0][ma0] = a0;
        *(float4*)&As[ka1][ma0] = a1;
        *(float4*)&Bs[kb][nb] = b0;
        __syncthreads();
#pragma unroll
        for (int kk = 0; kk < 16; kk++) {
            float a[8], bb[4];
            *(float4*)(a)     = *(const float4*)&As[kk][ty * 8];
            *(float4*)(a + 4) = *(const float4*)&As[kk][ty * 8 + 4];
            *(float4*)(bb)    = *(const float4*)&Bs[kk][tx * 4];
#pragma unroll
            for (int i = 0; i < 8; i++)
#pragma unroll
                for (int j = 0; j < 4; j++)
                    acc[i][j] = fmaf(a[i], bb[j], acc[i][j]);
        }
    }
    __syncthreads();

#pragma unroll
    for (int i = 0; i < 8; i++)
#pragma unroll
        for (int j = 0; j < 4; j++)
            C[(long)(m0 + ty * 8 + i) * DHD + tx * 4 + j] = acc[i][j];
}

__global__ void reduce_ctx(const float* __restrict__ p, float* __restrict__ c) {
    int i = blockIdx.x * 256 + threadIdx.x;   // 64*256*64 = 1048576 total
    c[i] = (p[i] + p[i + 1048576]) + (p[i + 2097152] + p[i + 3145728]);
}

// -------------------- elementwise / reduction kernels ----------------------
__global__ void transpose_proj(const float* __restrict__ proj, float* __restrict__ projT) {
    int i = blockIdx.x * 256 + threadIdx.x;   // 16384
    int m = i >> 6, d = i & 63;
    projT[d * MF + m] = proj[i];
}

// partial max over dashK per (b,h): grid (16 chunks, 64 bh)
__global__ void max_part(const float* __restrict__ dK, float* __restrict__ part) {
    int chunk = blockIdx.x, bh = blockIdx.y, t = threadIdx.x;
    const float* p = dK + (long)bh * (NK * MF) + chunk * 65536;
    float m = -1e30f;
    for (int i = t; i < 65536; i += 256) m = fmaxf(m, p[i]);
    m = blockMax256(m);
    if (t == 0) part[bh * 16 + chunk] = m;
}

__global__ void finalize_max(const float* __restrict__ part, float* __restrict__ stab) {
    int t = threadIdx.x;   // 64
    float m = -1e30f;
#pragma unroll
    for (int i = 0; i < 16; i++) m = fmaxf(m, part[t * 16 + i]);
    stab[t] = m;
}

// qp = ratio*(exp(dashQ - diag - rowmax) + eps), in-place. One block per row.
__global__ void phi_q(const float* __restrict__ Q, float* __restrict__ dq) {
    int r = blockIdx.x;       // 0..65535
    int t = threadIdx.x;      // 256
    int bh = r >> 10, n = r & 1023;
    int b = bh >> 3, h = bh & 7;
    float val = dq[(long)r * MF + t];
    float x = 0.f;
    if (t < DHD) x = Q[((long)(b * NQ + n)) * DMODEL + h * DHD + t];
    float ss = blockSum256(x * x);
    float mx = blockMax256(val);
    dq[(long)r * MF + t] = RATIO * (expf(val - ss * 0.0625f - mx) + EPSF);
}

// kp = ratio*(exp(dashK - diag - stabK[bh]) + eps), in-place.
__global__ void phi_k(const float* __restrict__ K, float* __restrict__ dk,
                      const float* __restrict__ stabK) {
    int r = blockIdx.x;       // 0..262143
    int t = threadIdx.x;
    int bh = r >> 12, s = r & 4095;
    int b = bh >> 3, h = bh & 7;
    float val = dk[(long)r * MF + t];
    float x = 0.f;
    if (t < DHD) x = K[((long)(b * NK + s)) * DMODEL + h * DHD + t];
    float ss = blockSum256(x * x);
    float stab = stabK[bh];
    dk[(long)r * MF + t] = RATIO * (expf(val - ss * 0.0625f - stab) + EPSF);
}

// k_cumsum partials: grid (4 splits, 64 bh), thread = m
__global__ void kc_part(const float* __restrict__ kp, float* __restrict__ part) {
    int sp = blockIdx.x, bh = blockIdx.y, t = threadIdx.x;
    const float* p = kp + ((long)bh * NK + sp * 1024) * MF + t;
    float s0 = 0, s1 = 0, s2 = 0, s3 = 0;
    for (int i = 0; i < 1024; i += 4) {
        s0 += p[(long)(i + 0) * MF];
        s1 += p[(long)(i + 1) * MF];
        s2 += p[(long)(i + 2) * MF];
        s3 += p[(long)(i + 3) * MF];
    }
    part[(sp * BHN + bh) * MF + t] = (s0 + s1) + (s2 + s3);
}

__global__ void kc_final(const float* __restrict__ part, float* __restrict__ kc) {
    int bh = blockIdx.x, t = threadIdx.x;
    float s = 0.f;
#pragma unroll
    for (int sp = 0; sp < 4; sp++) s += part[(sp * BHN + bh) * MF + t];
    kc[bh * MF + t] = s;
}

// denom = qp . kc, attn[b,n,h*64+d] = tmp / denom. One block per (bh,n) row.
__global__ void scale_out(const float* __restrict__ qp, const float* __restrict__ kc,
                          const float* __restrict__ tmp, float* __restrict__ attn) {
    int r = blockIdx.x;       // 65536
    int t = threadIdx.x;
    int bh = r >> 10, n = r & 1023;
    int b = bh >> 3, h = bh & 7;
    float d = blockSum256(qp[(long)r * MF + t] * kc[bh * MF + t]);
    if (t < DHD)
        attn[((long)(b * NQ + n)) * DMODEL + h * DHD + t] = tmp[(long)r * DHD + t] / d;
}

// ---------------------------------------------------------------------------
extern "C" void kernel_launch(void* const* d_in, const int* in_sizes, int n_in,
                              void* d_out, int out_size)
{
    (void)in_sizes; (void)n_in; (void)out_size;
    const float* x       = (const float*)d_in[0];
    const float* context = (const float*)d_in[1];
    const float* Wq      = (const float*)d_in[2];
    const float* Wk      = (const float*)d_in[3];
    const float* Wv      = (const float*)d_in[4];
    const float* Wo      = (const float*)d_in[5];
    const float* bo      = (const float*)d_in[6];
    const float* proj    = (const float*)d_in[7];
    float* out = (float*)d_out;

    float *Q, *K, *V, *projT, *qp, *kp, *maxPart, *stabK, *kcPart, *kc;
    float *ctxPart, *ctx, *tmp, *attn;
    cudaGetSymbolAddress((void**)&Q, g_Q);
    cudaGetSymbolAddress((void**)&K, g_K);
    cudaGetSymbolAddress((void**)&V, g_V);
    cudaGetSymbolAddress((void**)&projT, g_projT);
    cudaGetSymbolAddress((void**)&qp, g_qp);
    cudaGetSymbolAddress((void**)&kp, g_kp);
    cudaGetSymbolAddress((void**)&maxPart, g_maxPart);
    cudaGetSymbolAddress((void**)&stabK, g_stabK);
    cudaGetSymbolAddress((void**)&kcPart, g_kcPart);
    cudaGetSymbolAddress((void**)&kc, g_kc);
    cudaGetSymbolAddress((void**)&ctxPart, g_ctxPart);
    cudaGetSymbolAddress((void**)&ctx, g_ctx);
    cudaGetSymbolAddress((void**)&tmp, g_tmp);
    cudaGetSymbolAddress((void**)&attn, g_attn);

    // proj -> projT [64][256]
    transpose_proj<<<64, 256>>>(proj, projT);

    // Q/K/V projections
    sgemm_nn<<<dim3(4, 64, 1), 256>>>(x, Wq, Q, nullptr,
        BATCH * NQ, DMODEL, DMODEL, DMODEL, DMODEL, DMODEL,
        1, 0, 0, 0, 0, 0, 0, 1.f);
    sgemm_nn<<<dim3(4, 256, 1), 256>>>(context, Wk, K, nullptr,
        BATCH * NK, DMODEL, DMODEL, DMODEL, DMODEL, DMODEL,
        1, 0, 0, 0, 0, 0, 0, 1.f);
    sgemm_nn<<<dim3(4, 256, 1), 256>>>(context, Wv, V, nullptr,
        BATCH * NK, DMODEL, DMODEL, DMODEL, DMODEL, DMODEL,
        1, 0, 0, 0, 0, 0, 0, 1.f);

    // dashQ[b,h,n,m] = dn * (Q_head @ projT)
    sgemm_nn<<<dim3(2, 8, 64), 256>>>(Q, projT, qp, nullptr,
        NQ, MF, DHD, DMODEL, MF, MF,
        NH, (long)NQ * DMODEL, DHD, 0, 0,
        (long)NH * NQ * MF, (long)NQ * MF, DN_SCALE);

    // dashK[b,h,s,m]
    sgemm_nn<<<dim3(2, 32, 64), 256>>>(K, projT, kp, nullptr,
        NK, MF, DHD, DMODEL, MF, MF,
        NH, (long)NK * DMODEL, DHD, 0, 0,
        (long)NH * NK * MF, (long)NK * MF, DN_SCALE);

    // global max per (b,h) for key stabilizer
    max_part<<<dim3(16, 64), 256>>>(kp, maxPart);
    finalize_max<<<1, 64>>>(maxPart, stabK);

    // feature maps (in-place exp)
    phi_q<<<BHN * NQ, 256>>>(Q, qp);
    phi_k<<<BHN * NK, 256>>>(K, kp, stabK);

    // k_cumsum
    kc_part<<<dim3(4, 64), 256>>>(kp, kcPart);
    kc_final<<<64, 256>>>(kcPart, kc);

    // ctx = kp^T @ V (split-K=4)
    ctx_tn<<<dim3(2, 1, 256), 256>>>(kp, V, ctxPart);
    reduce_ctx<<<4096, 256>>>(ctxPart, ctx);

    // tmp = qp @ ctx  (per head)
    sgemm_nn<<<dim3(1, 8, 64), 256>>>(qp, ctx, tmp, nullptr,
        NQ, DHD, MF, MF, DHD, DHD,
        BHN, 0, (long)NQ * MF, 0, (long)MF * DHD,
        0, (long)NQ * DHD, 1.f);

    // normalize + head merge
    scale_out<<<BHN * NQ, 256>>>(qp, kc, tmp, attn);

    // final projection + bias
    sgemm_nn<<<dim3(4, 64, 1), 256>>>(attn, Wo, out, bo,
        BATCH * NQ, DMODEL, DMODEL, DMODEL, DMODEL, DMODEL,
        1, 0, 0, 0, 0, 0, 0, 1.f);
}

// round 2
// speedup vs baseline: 1.0077x; 1.0077x over previous
#include <cuda_runtime.h>
#include <math.h>

// ---------------------------------------------------------------------------
// Performer FAVOR+ cross-attention forward, fp32 baseline.
// B=8, Nq=1024, Nk=4096, D=512, H=8, DH=64, M=256
// ---------------------------------------------------------------------------

#define BATCH 8
#define NQ 1024
#define NK 4096
#define DMODEL 512
#define NH 8
#define DHD 64
#define MF 256
#define BHN 64          // BATCH * NH

#define DN_SCALE 0.35355339059327379f  // 64^-0.25
#define RATIO 0.0625f                  // 256^-0.5
#define EPSF 1e-4f

// -------------------- scratch (static device allocations) ------------------
__device__ float g_Q[BATCH * NQ * DMODEL];          // 16 MB
__device__ float g_K[BATCH * NK * DMODEL];          // 64 MB
__device__ float g_V[BATCH * NK * DMODEL];          // 64 MB
__device__ float g_projT[DHD * MF];                 // proj transposed [64][256]
__device__ float g_qp[BHN * NQ * MF];               // dashQ -> qp, 64 MB
__device__ float g_kp[(size_t)BHN * NK * MF];       // dashK -> kp, 256 MB
__device__ float g_maxPart[BHN * 16];
__device__ float g_stabK[BHN];
__device__ float g_kcPart[4 * BHN * MF];
__device__ float g_kc[BHN * MF];
__device__ float g_ctxPart[4 * BHN * MF * DHD];     // 16 MB
__device__ float g_ctx[BHN * MF * DHD];             // 4 MB
__device__ float g_tmp[BHN * NQ * DHD];             // 16 MB
__device__ float g_attn[BATCH * NQ * DMODEL];       // 16 MB

// -------------------- block reduction helpers (256 threads) ----------------
__device__ __forceinline__ float warpRedSum(float v) {
#pragma unroll
    for (int o = 16; o > 0; o >>= 1) v += __shfl_xor_sync(0xffffffffu, v, o);
    return v;
}
__device__ __forceinline__ float warpRedMax(float v) {
#pragma unroll
    for (int o = 16; o > 0; o >>= 1) v = fmaxf(v, __shfl_xor_sync(0xffffffffu, v, o));
    return v;
}
__device__ __forceinline__ float blockSum256(float v) {
    __shared__ float sh[8];
    v = warpRedSum(v);
    int lane = threadIdx.x & 31, w = threadIdx.x >> 5;
    if (lane == 0) sh[w] = v;
    __syncthreads();
    float s = sh[0];
#pragma unroll
    for (int i = 1; i < 8; i++) s += sh[i];
    return s;
}
__device__ __forceinline__ float blockMax256(float v) {
    __shared__ float sh[8];
    v = warpRedMax(v);
    int lane = threadIdx.x & 31, w = threadIdx.x >> 5;
    if (lane == 0) sh[w] = v;
    __syncthreads();
    float m = sh[0];
#pragma unroll
    for (int i = 1; i < 8; i++) m = fmaxf(m, sh[i]);
    return m;
}

// -------------------- generic SGEMM (NN), 128x128x8, 256 thr, 8x8/thr ------
// C = alpha * A[M,K] @ B[K,N] (+ bias), row-major, batched over grid.z:
//   off = (z / Hd) * off*b + (z % Hd) * off*h
// Requirements: M % 128 == 0, K % 8 == 0, N % 4 == 0 (N may be < 128, guarded).
__global__ __launch_bounds__(256) void sgemm_nn(
    const float* __restrict__ A, const float* __restrict__ B,
    float* __restrict__ C, const float* __restrict__ bias,
    int M, int N, int K, int lda, int ldb, int ldc,
    int Hd, long offAb, long offAh, long offBb, long offBh,
    long offCb, long offCh, float alpha)
{
    int z = blockIdx.z;
    int zb = z / Hd, zh = z % Hd;
    A += (long)zb * offAb + (long)zh * offAh;
    B += (long)zb * offBb + (long)zh * offBh;
    C += (long)zb * offCb + (long)zh * offCh;

    __shared__ float As[8][128];
    __shared__ float Bs[8][128];

    int tid = threadIdx.x;
    int m0 = blockIdx.y * 128;
    int n0 = blockIdx.x * 128;

    int arow = tid >> 1;             // 0..127
    int ak = (tid & 1) * 4;          // 0 or 4
    int brow = tid >> 5;             // 0..7
    int bcol = (tid & 31) * 4;       // 0..124

    int tx = tid & 15;               // n dir
    int ty = tid >> 4;               // m dir

    float acc[8][8];
#pragma unroll
    for (int i = 0; i < 8; i++)
#pragma unroll
        for (int j = 0; j < 8; j++) acc[i][j] = 0.f;

    for (int k0 = 0; k0 < K; k0 += 8) {
        float4 av = *(const float4*)(A + (long)(m0 + arow) * lda + k0 + ak);
        float4 bv = make_float4(0.f, 0.f, 0.f, 0.f);
        if (n0 + bcol < N)
            bv = *(const float4*)(B + (long)(k0 + brow) * ldb + n0 + bcol);
        __syncthreads();
        As[ak + 0][arow] = av.x;
        As[ak + 1][arow] = av.y;
        As[ak + 2][arow] = av.z;
        As[ak + 3][arow] = av.w;
        *(float4*)&Bs[brow][bcol] = bv;
        __syncthreads();
#pragma unroll
        for (int kk = 0; kk < 8; kk++) {
            float a[8], b[8];
            *(float4*)(a)     = *(const float4*)&As[kk][ty * 8];
            *(float4*)(a + 4) = *(const float4*)&As[kk][ty * 8 + 4];
            *(float4*)(b)     = *(const float4*)&Bs[kk][tx * 8];
            *(float4*)(b + 4) = *(const float4*)&Bs[kk][tx * 8 + 4];
#pragma unroll
            for (int i = 0; i < 8; i++)
#pragma unroll
                for (int j = 0; j < 8; j++)
                    acc[i][j] = fmaf(a[i], b[j], acc[i][j]);
        }
    }
    __syncthreads();

#pragma unroll
    for (int i = 0; i < 8; i++) {
        int m = m0 + ty * 8 + i;
#pragma unroll
        for (int j = 0; j < 8; j += 4) {
            int n = n0 + tx * 8 + j;
            if (n < N) {
                float4 v;
                v.x = alpha * acc[i][j + 0];
                v.y = alpha * acc[i][j + 1];
                v.z = alpha * acc[i][j + 2];
                v.w = alpha * acc[i][j + 3];
                if (bias) {
                    v.x += bias[n]; v.y += bias[n + 1];
                    v.z += bias[n + 2]; v.w += bias[n + 3];
                }
                *(float4*)(C + (long)m * ldc + n) = v;
            }
        }
    }
}

// -------------------- ctx = kp^T @ V (TN GEMM, hardcoded) -------------------
// Per (b,h): ctx[m,d] = sum_s kp[s,m] * V[s,d].  kp stored [s,256] (== [K,M]).
// grid: x = m-block (2), z = split*64 + bh. Split-K=4 (1024 rows each).
__global__ __launch_bounds__(256) void ctx_tn(
    const float* __restrict__ KP, const float* __restrict__ V,
    float* __restrict__ Cp)
{
    int z = blockIdx.z;
    int split = z >> 6, bh = z & 63;
    int b = bh >> 3, h = bh & 7;
    const float* A = KP + (long)bh * NK * MF + (long)split * 1024 * MF; // [1024,256]
    const float* B = V + ((long)b * NK + split * 1024) * DMODEL + h * DHD;
    float* C = Cp + ((long)split * BHN + bh) * MF * DHD;
    int m0 = blockIdx.x * 128;

    __shared__ float As[16][128];
    __shared__ float Bs[16][64];
    int tid = threadIdx.x;
    int tx = tid & 15;   // n: 4 each
    int ty = tid >> 4;   // m: 8 each

    float acc[8][4];
#pragma unroll
    for (int i = 0; i < 8; i++)
#pragma unroll
        for (int j = 0; j < 4; j++) acc[i][j] = 0.f;

    int ka0 = tid >> 5, ma0 = (tid & 31) * 4;            // A pieces
    int ka1 = (tid + 256) >> 5;                          // = ka0 + 8
    int kb = tid >> 4, nb = (tid & 15) * 4;              // B piece

    for (int k0 = 0; k0 < 1024; k0 += 16) {
        float4 a0 = *(const float4*)(A + (long)(k0 + ka0) * MF + m0 + ma0);
        float4 a1 = *(const float4*)(A + (long)(k0 + ka1) * MF + m0 + ma0);
        float4 b0 = *(const float4*)(B + (long)(k0 + kb) * DMODEL + nb);
        __syncthreads();
        *(float4*)&As[ka0][ma0] = a0;
        *(float4*)&As[ka1][ma0] = a1;
        *(float4*)&Bs[kb][nb] = b0;
        __syncthreads();
#pragma unroll
        for (int kk = 0; kk < 16; kk++) {
            float a[8], bb[4];
            *(float4*)(a)     = *(const float4*)&As[kk][ty * 8];
            *(float4*)(a + 4) = *(const float4*)&As[kk][ty * 8 + 4];
            *(float4*)(bb)    = *(const float4*)&Bs[kk][tx * 4];
#pragma unroll
            for (int i = 0; i < 8; i++)
#pragma unroll
                for (int j = 0; j < 4; j++)
                    acc[i][j] = fmaf(a[i], bb[j], acc[i][j]);
        }
    }
    __syncthreads();

#pragma unroll
    for (int i = 0; i < 8; i++)
#pragma unroll
        for (int j = 0; j < 4; j++)
            C[(long)(m0 + ty * 8 + i) * DHD + tx * 4 + j] = acc[i][j];
}

__global__ void reduce_ctx(const float* __restrict__ p, float* __restrict__ c) {
    int i = blockIdx.x * 256 + threadIdx.x;   // 64*256*64 = 1048576 total
    c[i] = (p[i] + p[i + 1048576]) + (p[i + 2097152] + p[i + 3145728]);
}

// -------------------- elementwise / reduction kernels ----------------------
__global__ void transpose_proj(const float* __restrict__ proj, float* __restrict__ projT) {
    int i = blockIdx.x * 256 + threadIdx.x;   // 16384
    int m = i >> 6, d = i & 63;
    projT[d * MF + m] = proj[i];
}

// partial max over dashK per (b,h): grid (16 chunks, 64 bh)
__global__ void max_part(const float* __restrict__ dK, float* __restrict__ part) {
    int chunk = blockIdx.x, bh = blockIdx.y, t = threadIdx.x;
    const float* p = dK + (long)bh * (NK * MF) + chunk * 65536;
    float m = -1e30f;
    for (int i = t; i < 65536; i += 256) m = fmaxf(m, p[i]);
    m = blockMax256(m);
    if (t == 0) part[bh * 16 + chunk] = m;
}

__global__ void finalize_max(const float* __restrict__ part, float* __restrict__ stab) {
    int t = threadIdx.x;   // 64
    float m = -1e30f;
#pragma unroll
    for (int i = 0; i < 16; i++) m = fmaxf(m, part[t * 16 + i]);
    stab[t] = m;
}

// qp = ratio*(exp(dashQ - diag - rowmax) + eps), in-place. One block per row.
__global__ void phi_q(const float* __restrict__ Q, float* __restrict__ dq) {
    int r = blockIdx.x;       // 0..65535
    int t = threadIdx.x;      // 256
    int bh = r >> 10, n = r & 1023;
    int b = bh >> 3, h = bh & 7;
    float val = dq[(long)r * MF + t];
    float x = 0.f;
    if (t < DHD) x = Q[((long)(b * NQ + n)) * DMODEL + h * DHD + t];
    float ss = blockSum256(x * x);
    float mx = blockMax256(val);
    dq[(long)r * MF + t] = RATIO * (expf(val - ss * 0.0625f - mx) + EPSF);
}

// kp = ratio*(exp(dashK - diag - stabK[bh]) + eps), in-place.
__global__ void phi_k(const float* __restrict__ K, float* __restrict__ dk,
                      const float* __restrict__ stabK) {
    int r = blockIdx.x;       // 0..262143
    int t = threadIdx.x;
    int bh = r >> 12, s = r & 4095;
    int b = bh >> 3, h = bh & 7;
    float val = dk[(long)r * MF + t];
    float x = 0.f;
    if (t < DHD) x = K[((long)(b * NK + s)) * DMODEL + h * DHD + t];
    float ss = blockSum256(x * x);
    float stab = stabK[bh];
    dk[(long)r * MF + t] = RATIO * (expf(val - ss * 0.0625f - stab) + EPSF);
}

// k_cumsum partials: grid (4 splits, 64 bh), thread = m
__global__ void kc_part(const float* __restrict__ kp, float* __restrict__ part) {
    int sp = blockIdx.x, bh = blockIdx.y, t = threadIdx.x;
    const float* p = kp + ((long)bh * NK + sp * 1024) * MF + t;
    float s0 = 0, s1 = 0, s2 = 0, s3 = 0;
    for (int i = 0; i < 1024; i += 4) {
        s0 += p[(long)(i + 0) * MF];
        s1 += p[(long)(i + 1) * MF];
        s2 += p[(long)(i + 2) * MF];
        s3 += p[(long)(i + 3) * MF];
    }
    part[(sp * BHN + bh) * MF + t] = (s0 + s1) + (s2 + s3);
}

__global__ void kc_final(const float* __restrict__ part, float* __restrict__ kc) {
    int bh = blockIdx.x, t = threadIdx.x;
    float s = 0.f;
#pragma unroll
    for (int sp = 0; sp < 4; sp++) s += part[(sp * BHN + bh) * MF + t];
    kc[bh * MF + t] = s;
}

// denom = qp . kc, attn[b,n,h*64+d] = tmp / denom. One block per (bh,n) row.
__global__ void scale_out(const float* __restrict__ qp, const float* __restrict__ kc,
                          const float* __restrict__ tmp, float* __restrict__ attn) {
    int r = blockIdx.x;       // 65536
    int t = threadIdx.x;
    int bh = r >> 10, n = r & 1023;
    int b = bh >> 3, h = bh & 7;
    float d = blockSum256(qp[(long)r * MF + t] * kc[bh * MF + t]);
    if (t < DHD)
        attn[((long)(b * NQ + n)) * DMODEL + h * DHD + t] = tmp[(long)r * DHD + t] / d;
}

// ---------------------------------------------------------------------------
extern "C" void kernel_launch(void* const* d_in, const int* in_sizes, int n_in,
                              void* d_out, int out_size)
{
    (void)in_sizes; (void)n_in; (void)out_size;
    const float* x       = (const float*)d_in[0];
    const float* context = (const float*)d_in[1];
    const float* Wq      = (const float*)d_in[2];
    const float* Wk      = (const float*)d_in[3];
    const float* Wv      = (const float*)d_in[4];
    const float* Wo      = (const float*)d_in[5];
    const float* bo      = (const float*)d_in[6];
    const float* proj    = (const float*)d_in[7];
    float* out = (float*)d_out;

    float *Q, *K, *V, *projT, *qp, *kp, *maxPart, *stabK, *kcPart, *kc;
    float *ctxPart, *ctx, *tmp, *attn;
    cudaGetSymbolAddress((void**)&Q, g_Q);
    cudaGetSymbolAddress((void**)&K, g_K);
    cudaGetSymbolAddress((void**)&V, g_V);
    cudaGetSymbolAddress((void**)&projT, g_projT);
    cudaGetSymbolAddress((void**)&qp, g_qp);
    cudaGetSymbolAddress((void**)&kp, g_kp);
    cudaGetSymbolAddress((void**)&maxPart, g_maxPart);
    cudaGetSymbolAddress((void**)&stabK, g_stabK);
    cudaGetSymbolAddress((void**)&kcPart, g_kcPart);
    cudaGetSymbolAddress((void**)&kc, g_kc);
    cudaGetSymbolAddress((void**)&ctxPart, g_ctxPart);
    cudaGetSymbolAddress((void**)&ctx, g_ctx);
    cudaGetSymbolAddress((void**)&tmp, g_tmp);
    cudaGetSymbolAddress((void**)&attn, g_attn);

    // proj -> projT [64][256]
    transpose_proj<<<64, 256>>>(proj, projT);

    // Q/K/V projections
    sgemm_nn<<<dim3(4, 64, 1), 256>>>(x, Wq, Q, nullptr,
        BATCH * NQ, DMODEL, DMODEL, DMODEL, DMODEL, DMODEL,
        1, 0, 0, 0, 0, 0, 0, 1.f);
    sgemm_nn<<<dim3(4, 256, 1), 256>>>(context, Wk, K, nullptr,
        BATCH * NK, DMODEL, DMODEL, DMODEL, DMODEL, DMODEL,
        1, 0, 0, 0, 0, 0, 0, 1.f);
    sgemm_nn<<<dim3(4, 256, 1), 256>>>(context, Wv, V, nullptr,
        BATCH * NK, DMODEL, DMODEL, DMODEL, DMODEL, DMODEL,
        1, 0, 0, 0, 0, 0, 0, 1.f);

    // dashQ[b,h,n,m] = dn * (Q_head @ projT)
    sgemm_nn<<<dim3(2, 8, 64), 256>>>(Q, projT, qp, nullptr,
        NQ, MF, DHD, DMODEL, MF, MF,
        NH, (long)NQ * DMODEL, DHD, 0, 0,
        (long)NH * NQ * MF, (long)NQ * MF, DN_SCALE);

    // dashK[b,h,s,m]
    sgemm_nn<<<dim3(2, 32, 64), 256>>>(K, projT, kp, nullptr,
        NK, MF, DHD, DMODEL, MF, MF,
        NH, (long)NK * DMODEL, DHD, 0, 0,
        (long)NH * NK * MF, (long)NK * MF, DN_SCALE);

    // global max per (b,h) for key stabilizer
    max_part<<<dim3(16, 64), 256>>>(kp, maxPart);
    finalize_max<<<1, 64>>>(maxPart, stabK);

    // feature maps (in-place exp)
    phi_q<<<BHN * NQ, 256>>>(Q, qp);
    phi_k<<<BHN * NK, 256>>>(K, kp, stabK);

    // k_cumsum
    kc_part<<<dim3(4, 64), 256>>>(kp, kcPart);
    kc_final<<<64, 256>>>(kcPart, kc);

    // ctx = kp^T @ V (split-K=4)
    ctx_tn<<<dim3(2, 1, 256), 256>>>(kp, V, ctxPart);
    reduce_ctx<<<4096, 256>>>(ctxPart, ctx);

    // tmp = qp @ ctx  (per head)
    sgemm_nn<<<dim3(1, 8, 64), 256>>>(qp, ctx, tmp, nullptr,
        NQ, DHD, MF, MF, DHD, DHD,
        BHN, 0, (long)NQ * MF, 0, (long)MF * DHD,
        0, (long)NQ * DHD, 1.f);

    // normalize + head merge
    scale_out<<<BHN * NQ, 256>>>(qp, kc, tmp, attn);

    // final projection + bias
    sgemm_nn<<<dim3(4, 64, 1), 256>>>(attn, Wo, out, bo,
        BATCH * NQ, DMODEL, DMODEL, DMODEL, DMODEL, DMODEL,
        1, 0, 0, 0, 0, 0, 0, 1.f);
}

// round 3
// speedup vs baseline: 1.8705x; 1.8563x over previous
#include <cuda_runtime.h>
#include <math.h>
#include <stdint.h>

// ---------------------------------------------------------------------------
// Performer FAVOR+ cross-attention forward.
// B=8, Nq=1024, Nk=4096, D=512, H=8, DH=64, M=256
// Round 2: all GEMMs on tensor cores (mma.sync tf32, fp32 accumulate).
// ---------------------------------------------------------------------------

#define BATCH 8
#define NQ 1024
#define NK 4096
#define DMODEL 512
#define NH 8
#define DHD 64
#define MF 256
#define BHN 64          // BATCH * NH

#define DN_SCALE 0.35355339059327379f  // 64^-0.25
#define RATIO 0.0625f                  // 256^-0.5
#define EPSF 1e-4f

// -------------------- scratch (static device allocations) ------------------
__device__ float g_Q[BATCH * NQ * DMODEL];          // 16 MB
__device__ float g_K[BATCH * NK * DMODEL];          // 64 MB
__device__ float g_V[BATCH * NK * DMODEL];          // 64 MB
__device__ float g_projT[DHD * MF];                 // proj transposed [64][256]
__device__ float g_qp[BHN * NQ * MF];               // dashQ -> qp, 64 MB
__device__ float g_kp[(size_t)BHN * NK * MF];       // dashK -> kp, 256 MB
__device__ float g_maxPart[BHN * 16];
__device__ float g_stabK[BHN];
__device__ float g_kcPart[4 * BHN * MF];
__device__ float g_kc[BHN * MF];
__device__ float g_ctxPart[4 * BHN * MF * DHD];     // 16 MB
__device__ float g_ctx[BHN * MF * DHD];             // 4 MB
__device__ float g_tmp[BHN * NQ * DHD];             // 16 MB
__device__ float g_attn[BATCH * NQ * DMODEL];       // 16 MB

// -------------------- helpers ----------------------------------------------
__device__ __forceinline__ uint32_t f2tf32(float f) {
    uint32_t u;
    asm("cvt.rna.tf32.f32 %0, %1;" : "=r"(u) : "f"(f));
    return u;
}

#define MMA_TF32(d, a, b)                                               \
    asm volatile(                                                       \
        "mma.sync.aligned.m16n8k8.row.col.f32.tf32.tf32.f32 "           \
        "{%0,%1,%2,%3}, {%4,%5,%6,%7}, {%8,%9}, {%0,%1,%2,%3};\n"       \
        : "+f"(d[0]), "+f"(d[1]), "+f"(d[2]), "+f"(d[3])                \
        : "r"(a[0]), "r"(a[1]), "r"(a[2]), "r"(a[3]),                   \
          "r"(b[0]), "r"(b[1]))

__device__ __forceinline__ float warpRedSum(float v) {
#pragma unroll
    for (int o = 16; o > 0; o >>= 1) v += __shfl_xor_sync(0xffffffffu, v, o);
    return v;
}
__device__ __forceinline__ float warpRedMax(float v) {
#pragma unroll
    for (int o = 16; o > 0; o >>= 1) v = fmaxf(v, __shfl_xor_sync(0xffffffffu, v, o));
    return v;
}
__device__ __forceinline__ float blockSum256(float v) {
    __shared__ float sh[8];
    v = warpRedSum(v);
    int lane = threadIdx.x & 31, w = threadIdx.x >> 5;
    if (lane == 0) sh[w] = v;
    __syncthreads();
    float s = sh[0];
#pragma unroll
    for (int i = 1; i < 8; i++) s += sh[i];
    return s;
}
__device__ __forceinline__ float blockMax256(float v) {
    __shared__ float sh[8];
    v = warpRedMax(v);
    int lane = threadIdx.x & 31, w = threadIdx.x >> 5;
    if (lane == 0) sh[w] = v;
    __syncthreads();
    float m = sh[0];
#pragma unroll
    for (int i = 1; i < 8; i++) m = fmaxf(m, sh[i]);
    return m;
}

// ---------------------------------------------------------------------------
// TF32 tensor-core GEMM: C = alpha * op(A) @ B (+ bias), row-major.
//   TRANSA=false: A is [M,K] with leading dim lda.
//   TRANSA=true : A is [K,M] with leading dim lda (computes A^T @ B).
// Block tile 128(M) x 128(N) x 16(K), 256 threads, 8 warps (2x4),
// warp tile 64x32, mma m16n8k8, double-buffered smem.
// Requirements: M % 128 == 0, K % 16 == 0. N guarded (zero-filled B, masked C).
// Batched over grid.z via 3-level decomposition z = (z1*d2 + z2)*d3 + z3.
// ---------------------------------------------------------------------------
template <bool TRANSA>
__global__ __launch_bounds__(256) void tmma_gemm(
    const float* __restrict__ A, const float* __restrict__ B,
    float* __restrict__ C, const float* __restrict__ bias,
    int M, int N, int K, int lda, int ldb, int ldc,
    int d2, int d3,
    long oA1, long oA2, long oA3,
    long oB1, long oB2, long oB3,
    long oC1, long oC2, long oC3,
    float alpha)
{
    {
        int z = blockIdx.z;
        int z3 = z % d3;
        int zq = z / d3;
        int z2 = zq % d2;
        int z1 = zq / d2;
        A += z1 * oA1 + z2 * oA2 + z3 * oA3;
        B += z1 * oB1 + z2 * oB2 + z3 * oB3;
        C += z1 * oC1 + z2 * oC2 + z3 * oC3;
    }

    __shared__ uint32_t As[2][16][136];   // [k][m], pad 8 -> conflict-free frags
    __shared__ uint32_t Bs[2][16][136];   // [k][n]

    const int tid = threadIdx.x;
    const int lane = tid & 31;
    const int warp = tid >> 5;
    const int warpM = warp >> 2;          // 0..1
    const int warpN = warp & 3;           // 0..3
    const int gid = lane >> 2;            // 0..7
    const int tig = lane & 3;             // 0..3

    const int m0 = blockIdx.y * 128;
    const int n0 = blockIdx.x * 128;

    // global load coords
    const int a_r = tid >> 1;             // NN: row within tile (0..127)
    const int a_c = (tid & 1) * 4;        // NN: k offset 0 or 4 (second at +8)
    const int a_k = tid >> 4;             // TN: k row (0..15)
    const int a_m = (tid & 15) * 4;       // TN: m col (second at +64)
    const int b_k = tid >> 4;             // 0..15
    const int b_n = (tid & 15) * 4;       // second at +64

    float acc[4][4][4];
#pragma unroll
    for (int i = 0; i < 4; i++)
#pragma unroll
        for (int j = 0; j < 4; j++)
#pragma unroll
            for (int r = 0; r < 4; r++) acc[i][j][r] = 0.f;

    const int ntiles = K >> 4;
    float4 pa0, pa1, pb0, pb1;
    const float4 f4z = make_float4(0.f, 0.f, 0.f, 0.f);

    // ---- prologue: load tile 0 ----
    if (!TRANSA) {
        const float* Ap = A + (long)(m0 + a_r) * lda + a_c;
        pa0 = *(const float4*)Ap;
        pa1 = *(const float4*)(Ap + 8);
    } else {
        const float* Ap = A + (long)a_k * lda + m0 + a_m;
        pa0 = *(const float4*)Ap;
        pa1 = *(const float4*)(Ap + 64);
    }
    {
        const float* Bp = B + (long)b_k * ldb + n0 + b_n;
        pb0 = (n0 + b_n < N) ? *(const float4*)Bp : f4z;
        pb1 = (n0 + b_n + 64 < N) ? *(const float4*)(Bp + 64) : f4z;
    }
    if (!TRANSA) {
        As[0][a_c + 0][a_r] = f2tf32(pa0.x);
        As[0][a_c + 1][a_r] = f2tf32(pa0.y);
        As[0][a_c + 2][a_r] = f2tf32(pa0.z);
        As[0][a_c + 3][a_r] = f2tf32(pa0.w);
        As[0][a_c + 8][a_r] = f2tf32(pa1.x);
        As[0][a_c + 9][a_r] = f2tf32(pa1.y);
        As[0][a_c + 10][a_r] = f2tf32(pa1.z);
        As[0][a_c + 11][a_r] = f2tf32(pa1.w);
    } else {
        As[0][a_k][a_m + 0] = f2tf32(pa0.x);
        As[0][a_k][a_m + 1] = f2tf32(pa0.y);
        As[0][a_k][a_m + 2] = f2tf32(pa0.z);
        As[0][a_k][a_m + 3] = f2tf32(pa0.w);
        As[0][a_k][a_m + 64] = f2tf32(pa1.x);
        As[0][a_k][a_m + 65] = f2tf32(pa1.y);
        As[0][a_k][a_m + 66] = f2tf32(pa1.z);
        As[0][a_k][a_m + 67] = f2tf32(pa1.w);
    }
    Bs[0][b_k][b_n + 0] = f2tf32(pb0.x);
    Bs[0][b_k][b_n + 1] = f2tf32(pb0.y);
    Bs[0][b_k][b_n + 2] = f2tf32(pb0.z);
    Bs[0][b_k][b_n + 3] = f2tf32(pb0.w);
    Bs[0][b_k][b_n + 64] = f2tf32(pb1.x);
    Bs[0][b_k][b_n + 65] = f2tf32(pb1.y);
    Bs[0][b_k][b_n + 66] = f2tf32(pb1.z);
    Bs[0][b_k][b_n + 67] = f2tf32(pb1.w);
    __syncthreads();

    for (int kt = 0; kt < ntiles; kt++) {
        const int buf = kt & 1;
        const bool more = (kt + 1) < ntiles;
        // ---- prefetch next tile into registers ----
        if (more) {
            const int k0 = (kt + 1) * 16;
            if (!TRANSA) {
                const float* Ap = A + (long)(m0 + a_r) * lda + k0 + a_c;
                pa0 = *(const float4*)Ap;
                pa1 = *(const float4*)(Ap + 8);
            } else {
                const float* Ap = A + (long)(k0 + a_k) * lda + m0 + a_m;
                pa0 = *(const float4*)Ap;
                pa1 = *(const float4*)(Ap + 64);
            }
            const float* Bp = B + (long)(k0 + b_k) * ldb + n0 + b_n;
            pb0 = (n0 + b_n < N) ? *(const float4*)Bp : f4z;
            pb1 = (n0 + b_n + 64 < N) ? *(const float4*)(Bp + 64) : f4z;
        }
        // ---- compute on current buffer: two k8 steps ----
#pragma unroll
        for (int ks = 0; ks < 16; ks += 8) {
            uint32_t af[4][4], bf[4][2];
#pragma unroll
            for (int i = 0; i < 4; i++) {
                const int bm = warpM * 64 + i * 16;
                af[i][0] = As[buf][ks + tig][bm + gid];
                af[i][1] = As[buf][ks + tig][bm + gid + 8];
                af[i][2] = As[buf][ks + tig + 4][bm + gid];
                af[i][3] = As[buf][ks + tig + 4][bm + gid + 8];
            }
#pragma unroll
            for (int j = 0; j < 4; j++) {
                const int bn = warpN * 32 + j * 8;
                bf[j][0] = Bs[buf][ks + tig][bn + gid];
                bf[j][1] = Bs[buf][ks + tig + 4][bn + gid];
            }
#pragma unroll
            for (int i = 0; i < 4; i++)
#pragma unroll
                for (int j = 0; j < 4; j++)
                    MMA_TF32(acc[i][j], af[i], bf[j]);
        }
        // ---- store prefetched tile into other buffer ----
        if (more) {
            const int nb = buf ^ 1;
            if (!TRANSA) {
                As[nb][a_c + 0][a_r] = f2tf32(pa0.x);
                As[nb][a_c + 1][a_r] = f2tf32(pa0.y);
                As[nb][a_c + 2][a_r] = f2tf32(pa0.z);
                As[nb][a_c + 3][a_r] = f2tf32(pa0.w);
                As[nb][a_c + 8][a_r] = f2tf32(pa1.x);
                As[nb][a_c + 9][a_r] = f2tf32(pa1.y);
                As[nb][a_c + 10][a_r] = f2tf32(pa1.z);
                As[nb][a_c + 11][a_r] = f2tf32(pa1.w);
            } else {
                As[nb][a_k][a_m + 0] = f2tf32(pa0.x);
                As[nb][a_k][a_m + 1] = f2tf32(pa0.y);
                As[nb][a_k][a_m + 2] = f2tf32(pa0.z);
                As[nb][a_k][a_m + 3] = f2tf32(pa0.w);
                As[nb][a_k][a_m + 64] = f2tf32(pa1.x);
                As[nb][a_k][a_m + 65] = f2tf32(pa1.y);
                As[nb][a_k][a_m + 66] = f2tf32(pa1.z);
                As[nb][a_k][a_m + 67] = f2tf32(pa1.w);
            }
            Bs[nb][b_k][b_n + 0] = f2tf32(pb0.x);
            Bs[nb][b_k][b_n + 1] = f2tf32(pb0.y);
            Bs[nb][b_k][b_n + 2] = f2tf32(pb0.z);
            Bs[nb][b_k][b_n + 3] = f2tf32(pb0.w);
            Bs[nb][b_k][b_n + 64] = f2tf32(pb1.x);
            Bs[nb][b_k][b_n + 65] = f2tf32(pb1.y);
            Bs[nb][b_k][b_n + 66] = f2tf32(pb1.z);
            Bs[nb][b_k][b_n + 67] = f2tf32(pb1.w);
        }
        __syncthreads();
    }

    // ---- epilogue ----
#pragma unroll
    for (int i = 0; i < 4; i++) {
        const int row = m0 + warpM * 64 + i * 16 + gid;
#pragma unroll
        for (int j = 0; j < 4; j++) {
            const int col = n0 + warpN * 32 + j * 8 + 2 * tig;
            if (col < N) {
                float2 v0, v1;
                v0.x = alpha * acc[i][j][0];
                v0.y = alpha * acc[i][j][1];
                v1.x = alpha * acc[i][j][2];
                v1.y = alpha * acc[i][j][3];
                if (bias) {
                    float2 bv = *(const float2*)(bias + col);
                    v0.x += bv.x; v0.y += bv.y;
                    v1.x += bv.x; v1.y += bv.y;
                }
                *(float2*)(C + (long)row * ldc + col) = v0;
                *(float2*)(C + (long)(row + 8) * ldc + col) = v1;
            }
        }
    }
}

// -------------------- elementwise / reduction kernels ----------------------
__global__ void transpose_proj(const float* __restrict__ proj, float* __restrict__ projT) {
    int i = blockIdx.x * 256 + threadIdx.x;   // 16384
    int m = i >> 6, d = i & 63;
    projT[d * MF + m] = proj[i];
}

__global__ void reduce_ctx(const float* __restrict__ p, float* __restrict__ c) {
    int i = blockIdx.x * 256 + threadIdx.x;   // 64*256*64 = 1048576 total
    c[i] = (p[i] + p[i + 1048576]) + (p[i + 2097152] + p[i + 3145728]);
}

// partial max over dashK per (b,h): grid (16 chunks, 64 bh)
__global__ void max_part(const float* __restrict__ dK, float* __restrict__ part) {
    int chunk = blockIdx.x, bh = blockIdx.y, t = threadIdx.x;
    const float* p = dK + (long)bh * (NK * MF) + chunk * 65536;
    float m = -1e30f;
    for (int i = t; i < 65536; i += 256) m = fmaxf(m, p[i]);
    m = blockMax256(m);
    if (t == 0) part[bh * 16 + chunk] = m;
}

__global__ void finalize_max(const float* __restrict__ part, float* __restrict__ stab) {
    int t = threadIdx.x;   // 64
    float m = -1e30f;
#pragma unroll
    for (int i = 0; i < 16; i++) m = fmaxf(m, part[t * 16 + i]);
    stab[t] = m;
}

// qp = ratio*(exp(dashQ - diag - rowmax) + eps), in-place. One block per row.
__global__ void phi_q(const float* __restrict__ Q, float* __restrict__ dq) {
    int r = blockIdx.x;       // 0..65535
    int t = threadIdx.x;      // 256
    int bh = r >> 10, n = r & 1023;
    int b = bh >> 3, h = bh & 7;
    float val = dq[(long)r * MF + t];
    float x = 0.f;
    if (t < DHD) x = Q[((long)(b * NQ + n)) * DMODEL + h * DHD + t];
    float ss = blockSum256(x * x);
    float mx = blockMax256(val);
    dq[(long)r * MF + t] = RATIO * (expf(val - ss * 0.0625f - mx) + EPSF);
}

// kp = ratio*(exp(dashK - diag - stabK[bh]) + eps), in-place.
__global__ void phi_k(const float* __restrict__ K, float* __restrict__ dk,
                      const float* __restrict__ stabK) {
    int r = blockIdx.x;       // 0..262143
    int t = threadIdx.x;
    int bh = r >> 12, s = r & 4095;
    int b = bh >> 3, h = bh & 7;
    float val = dk[(long)r * MF + t];
    float x = 0.f;
    if (t < DHD) x = K[((long)(b * NK + s)) * DMODEL + h * DHD + t];
    float ss = blockSum256(x * x);
    float stab = stabK[bh];
    dk[(long)r * MF + t] = RATIO * (expf(val - ss * 0.0625f - stab) + EPSF);
}

// k_cumsum partials: grid (4 splits, 64 bh), thread = m
__global__ void kc_part(const float* __restrict__ kp, float* __restrict__ part) {
    int sp = blockIdx.x, bh = blockIdx.y, t = threadIdx.x;
    const float* p = kp + ((long)bh * NK + sp * 1024) * MF + t;
    float s0 = 0, s1 = 0, s2 = 0, s3 = 0;
    for (int i = 0; i < 1024; i += 4) {
        s0 += p[(long)(i + 0) * MF];
        s1 += p[(long)(i + 1) * MF];
        s2 += p[(long)(i + 2) * MF];
        s3 += p[(long)(i + 3) * MF];
    }
    part[(sp * BHN + bh) * MF + t] = (s0 + s1) + (s2 + s3);
}

__global__ void kc_final(const float* __restrict__ part, float* __restrict__ kc) {
    int bh = blockIdx.x, t = threadIdx.x;
    float s = 0.f;
#pragma unroll
    for (int sp = 0; sp < 4; sp++) s += part[(sp * BHN + bh) * MF + t];
    kc[bh * MF + t] = s;
}

// denom = qp . kc, attn[b,n,h*64+d] = tmp / denom. One block per (bh,n) row.
__global__ void scale_out(const float* __restrict__ qp, const float* __restrict__ kc,
                          const float* __restrict__ tmp, float* __restrict__ attn) {
    int r = blockIdx.x;       // 65536
    int t = threadIdx.x;
    int bh = r >> 10, n = r & 1023;
    int b = bh >> 3, h = bh & 7;
    float d = blockSum256(qp[(long)r * MF + t] * kc[bh * MF + t]);
    if (t < DHD)
        attn[((long)(b * NQ + n)) * DMODEL + h * DHD + t] = tmp[(long)r * DHD + t] / d;
}

// ---------------------------------------------------------------------------
extern "C" void kernel_launch(void* const* d_in, const int* in_sizes, int n_in,
                              void* d_out, int out_size)
{
    (void)in_sizes; (void)n_in; (void)out_size;
    const float* x       = (const float*)d_in[0];
    const float* context = (const float*)d_in[1];
    const float* Wq      = (const float*)d_in[2];
    const float* Wk      = (const float*)d_in[3];
    const float* Wv      = (const float*)d_in[4];
    const float* Wo      = (const float*)d_in[5];
    const float* bo      = (const float*)d_in[6];
    const float* proj    = (const float*)d_in[7];
    float* out = (float*)d_out;

    float *Q, *K, *V, *projT, *qp, *kp, *maxPart, *stabK, *kcPart, *kc;
    float *ctxPart, *ctx, *tmp, *attn;
    cudaGetSymbolAddress((void**)&Q, g_Q);
    cudaGetSymbolAddress((void**)&K, g_K);
    cudaGetSymbolAddress((void**)&V, g_V);
    cudaGetSymbolAddress((void**)&projT, g_projT);
    cudaGetSymbolAddress((void**)&qp, g_qp);
    cudaGetSymbolAddress((void**)&kp, g_kp);
    cudaGetSymbolAddress((void**)&maxPart, g_maxPart);
    cudaGetSymbolAddress((void**)&stabK, g_stabK);
    cudaGetSymbolAddress((void**)&kcPart, g_kcPart);
    cudaGetSymbolAddress((void**)&kc, g_kc);
    cudaGetSymbolAddress((void**)&ctxPart, g_ctxPart);
    cudaGetSymbolAddress((void**)&ctx, g_ctx);
    cudaGetSymbolAddress((void**)&tmp, g_tmp);
    cudaGetSymbolAddress((void**)&attn, g_attn);

    // proj -> projT [64][256]
    transpose_proj<<<64, 256>>>(proj, projT);

    // Q/K/V projections (tf32)
    tmma_gemm<false><<<dim3(4, 64, 1), 256>>>(x, Wq, Q, nullptr,
        BATCH * NQ, DMODEL, DMODEL, DMODEL, DMODEL, DMODEL,
        1, 1, 0, 0, 0, 0, 0, 0, 0, 0, 0, 1.f);
    tmma_gemm<false><<<dim3(4, 256, 1), 256>>>(context, Wk, K, nullptr,
        BATCH * NK, DMODEL, DMODEL, DMODEL, DMODEL, DMODEL,
        1, 1, 0, 0, 0, 0, 0, 0, 0, 0, 0, 1.f);
    tmma_gemm<false><<<dim3(4, 256, 1), 256>>>(context, Wv, V, nullptr,
        BATCH * NK, DMODEL, DMODEL, DMODEL, DMODEL, DMODEL,
        1, 1, 0, 0, 0, 0, 0, 0, 0, 0, 0, 1.f);

    // dashQ[b,h,n,m] = dn * (Q_head @ projT)  z = b*8 + h
    tmma_gemm<false><<<dim3(2, 8, 64), 256>>>(Q, projT, qp, nullptr,
        NQ, MF, DHD, DMODEL, MF, MF,
        8, 8,
        0, (long)NQ * DMODEL, DHD,
        0, 0, 0,
        0, (long)NH * NQ * MF, (long)NQ * MF,
        DN_SCALE);

    // dashK[b,h,s,m]
    tmma_gemm<false><<<dim3(2, 32, 64), 256>>>(K, projT, kp, nullptr,
        NK, MF, DHD, DMODEL, MF, MF,
        8, 8,
        0, (long)NK * DMODEL, DHD,
        0, 0, 0,
        0, (long)NH * NK * MF, (long)NK * MF,
        DN_SCALE);

    // global max per (b,h) for key stabilizer
    max_part<<<dim3(16, 64), 256>>>(kp, maxPart);
    finalize_max<<<1, 64>>>(maxPart, stabK);

    // feature maps (in-place exp)
    phi_q<<<BHN * NQ, 256>>>(Q, qp);
    phi_k<<<BHN * NK, 256>>>(K, kp, stabK);

    // k_cumsum
    kc_part<<<dim3(4, 64), 256>>>(kp, kcPart);
    kc_final<<<64, 256>>>(kcPart, kc);

    // ctx = kp^T @ V, split-K=4:  z = (split*8 + b)*8 + h
    tmma_gemm<true><<<dim3(1, 2, 256), 256>>>(kp, V, ctxPart, nullptr,
        MF, DHD, 1024, MF, DMODEL, DHD,
        8, 8,
        (long)1024 * MF, (long)8 * NK * MF, (long)NK * MF,
        (long)1024 * DMODEL, (long)NK * DMODEL, DHD,
        (long)BHN * MF * DHD, (long)8 * MF * DHD, (long)MF * DHD,
        1.f);
    reduce_ctx<<<4096, 256>>>(ctxPart, ctx);

    // tmp = qp @ ctx  (per bh)  z = b*8 + h
    tmma_gemm<false><<<dim3(1, 8, 64), 256>>>(qp, ctx, tmp, nullptr,
        NQ, DHD, MF, MF, DHD, DHD,
        8, 8,
        0, (long)8 * NQ * MF, (long)NQ * MF,
        0, (long)8 * MF * DHD, (long)MF * DHD,
        0, (long)8 * NQ * DHD, (long)NQ * DHD,
        1.f);

    // normalize + head merge
    scale_out<<<BHN * NQ, 256>>>(qp, kc, tmp, attn);

    // final projection + bias (tf32)
    tmma_gemm<false><<<dim3(4, 64, 1), 256>>>(attn, Wo, out, bo,
        BATCH * NQ, DMODEL, DMODEL, DMODEL, DMODEL, DMODEL,
        1, 1, 0, 0, 0, 0, 0, 0, 0, 0, 0, 1.f);
}

// round 4
// speedup vs baseline: 2.4384x; 1.3036x over previous
#include <cuda_runtime.h>
#include <math.h>
#include <stdint.h>

// ---------------------------------------------------------------------------
// Performer FAVOR+ cross-attention forward.
// B=8, Nq=1024, Nk=4096, D=512, H=8, DH=64, M=256
// Round 3: ldmatrix-based tf32 MMA GEMM (4 warps, 64x64 warp tiles),
//          fused stabilizer-max / k_cumsum / denominator passes.
// ---------------------------------------------------------------------------

#define BATCH 8
#define NQ 1024
#define NK 4096
#define DMODEL 512
#define NH 8
#define DHD 64
#define MF 256
#define BHN 64          // BATCH * NH

#define DN_SCALE 0.35355339059327379f  // 64^-0.25
#define RATIO 0.0625f                  // 256^-0.5
#define EPSF 1e-4f

// -------------------- scratch (static device allocations) ------------------
__device__ float g_Q[BATCH * NQ * DMODEL];          // 16 MB
__device__ float g_K[BATCH * NK * DMODEL];          // 64 MB
__device__ float g_V[BATCH * NK * DMODEL];          // 64 MB
__device__ float g_projT[DHD * MF];                 // proj transposed [64][256]
__device__ float g_qp[BHN * NQ * MF];               // dashQ -> qp, 64 MB
__device__ float g_kp[(size_t)BHN * NK * MF];       // dashK -> kp, 256 MB
__device__ unsigned g_stabEnc[BHN];
__device__ float g_kcPart[64 * BHN * MF];           // 4 MB
__device__ float g_kc[BHN * MF];
__device__ float g_denom[BHN * NQ];
__device__ float g_ctxPart[4 * BHN * MF * DHD];     // 16 MB
__device__ float g_ctx[BHN * MF * DHD];             // 4 MB
__device__ float g_attn[BATCH * NQ * DMODEL];       // 16 MB

// -------------------- helpers ----------------------------------------------
__device__ __forceinline__ uint32_t f2tf32(float f) {
    uint32_t u;
    asm("cvt.rna.tf32.f32 %0, %1;" : "=r"(u) : "f"(f));
    return u;
}

__device__ __forceinline__ unsigned encodeF(float f) {
    unsigned u = __float_as_uint(f);
    return (u & 0x80000000u) ? ~u : (u | 0x80000000u);
}
__device__ __forceinline__ float decodeF(unsigned e) {
    unsigned u = (e & 0x80000000u) ? (e ^ 0x80000000u) : ~e;
    return __uint_as_float(u);
}

#define MMA_TF32(d, a, b)                                               \
    asm volatile(                                                       \
        "mma.sync.aligned.m16n8k8.row.col.f32.tf32.tf32.f32 "           \
        "{%0,%1,%2,%3}, {%4,%5,%6,%7}, {%8,%9}, {%0,%1,%2,%3};\n"       \
        : "+f"(d[0]), "+f"(d[1]), "+f"(d[2]), "+f"(d[3])                \
        : "r"(a[0]), "r"(a[1]), "r"(a[2]), "r"(a[3]),                   \
          "r"(b[0]), "r"(b[1]))

#define LDSM4(r0, r1, r2, r3, addr)                                     \
    asm volatile(                                                       \
        "ldmatrix.sync.aligned.m8n8.x4.shared.b16 {%0,%1,%2,%3}, [%4];" \
        : "=r"(r0), "=r"(r1), "=r"(r2), "=r"(r3) : "r"(addr))

__device__ __forceinline__ float warpRedSum(float v) {
#pragma unroll
    for (int o = 16; o > 0; o >>= 1) v += __shfl_xor_sync(0xffffffffu, v, o);
    return v;
}
__device__ __forceinline__ float warpRedMax(float v) {
#pragma unroll
    for (int o = 16; o > 0; o >>= 1) v = fmaxf(v, __shfl_xor_sync(0xffffffffu, v, o));
    return v;
}
__device__ __forceinline__ float blockSum256(float v) {
    __shared__ float sh[8];
    v = warpRedSum(v);
    int lane = threadIdx.x & 31, w = threadIdx.x >> 5;
    __syncthreads();               // protect sh against previous call's readers
    if (lane == 0) sh[w] = v;
    __syncthreads();
    float s = sh[0];
#pragma unroll
    for (int i = 1; i < 8; i++) s += sh[i];
    return s;
}
__device__ __forceinline__ float blockMax256(float v) {
    __shared__ float sh[8];
    v = warpRedMax(v);
    int lane = threadIdx.x & 31, w = threadIdx.x >> 5;
    __syncthreads();
    if (lane == 0) sh[w] = v;
    __syncthreads();
    float m = sh[0];
#pragma unroll
    for (int i = 1; i < 8; i++) m = fmaxf(m, sh[i]);
    return m;
}

// ---------------------------------------------------------------------------
// TF32 tensor-core GEMM: C = alpha * op(A) @ B (+ bias) (/ rowdiv), row-major.
//   TRANSA=false: A is [M,K], lda.   TRANSA=true: A is [K,M], lda (A^T @ B).
// Block tile 128 x BN x 16, 128 threads (4 warps, 2x2), warp tile 64 x BN/2.
// Fragments via ldmatrix on m-major smem (16 k-words/row, pitch 20 words).
// All dims must tile exactly: M%128==0, N%BN==0, K%16==0.
// Batched over grid.z: z = (z1*d2 + z2)*d3 + z3.
// Optional: maxOut (atomicMax of encoded alpha*acc per z-index),
//           rowdiv (per-row divisor applied as 1/d multiply).
// ---------------------------------------------------------------------------
template <int BN, bool TRANSA>
__global__ __launch_bounds__(128, 2) void tmma2(
    const float* __restrict__ A, const float* __restrict__ B,
    float* __restrict__ C, const float* __restrict__ bias,
    const float* __restrict__ rowdiv, unsigned* __restrict__ maxOut,
    int K, int lda, int ldb, int ldc,
    int d2, int d3,
    long oA1, long oA2, long oA3,
    long oB1, long oB2, long oB3,
    long oC1, long oC2, long oC3,
    long oD2, long oD3,
    float alpha)
{
    constexpr int WN = BN / 2;     // warp n extent
    constexpr int NJ = WN / 8;     // n8 tiles per warp
    constexpr int NJJ = WN / 16;   // ldsm groups per warp

    {
        int z = blockIdx.z;
        int z3 = z % d3;
        int zq = z / d3;
        int z2 = zq % d2;
        int z1 = zq / d2;
        A += z1 * oA1 + z2 * oA2 + z3 * oA3;
        B += z1 * oB1 + z2 * oB2 + z3 * oB3;
        C += z1 * oC1 + z2 * oC2 + z3 * oC3;
        if (rowdiv) rowdiv += z2 * oD2 + z3 * oD3;
    }

    __shared__ uint32_t As[2][128][20];   // [m][k0..15 + 4 pad]
    __shared__ uint32_t Bs[2][BN][20];    // [n][k0..15 + 4 pad]
    __shared__ float redMax[4];

    const int tid = threadIdx.x;
    const int lane = tid & 31;
    const int warp = tid >> 5;
    const int warpM = warp >> 1;          // 0..1
    const int warpN = warp & 1;           // 0..1
    const int gid = lane >> 2;            // 0..7
    const int tig = lane & 3;             // 0..3

    const int m0 = blockIdx.y * 128;
    const int n0 = blockIdx.x * BN;

    const unsigned asU = (unsigned)__cvta_generic_to_shared(&As[0][0][0]);
    const unsigned bsU = (unsigned)__cvta_generic_to_shared(&Bs[0][0][0]);
    const int ldsmRow = (lane & 7) + ((lane >> 3) & 1) * 8;   // 0..15
    const int ldsmK   = (lane >> 4) * 4;                       // 0 or 4

    float acc[4][NJ][4];
#pragma unroll
    for (int i = 0; i < 4; i++)
#pragma unroll
        for (int j = 0; j < NJ; j++)
#pragma unroll
            for (int r = 0; r < 4; r++) acc[i][j][r] = 0.f;

    const int ntiles = K >> 4;
    float pa[16], pb[16];

    auto loadTile = [&](int k0) {
        if (!TRANSA) {
            const float* Ap = A + (long)(m0 + tid) * lda + k0;
            *(float4*)(pa + 0)  = *(const float4*)(Ap + 0);
            *(float4*)(pa + 4)  = *(const float4*)(Ap + 4);
            *(float4*)(pa + 8)  = *(const float4*)(Ap + 8);
            *(float4*)(pa + 12) = *(const float4*)(Ap + 12);
        } else {
            const float* Ap = A + (long)k0 * lda + m0 + tid;
#pragma unroll
            for (int k = 0; k < 16; k++) pa[k] = Ap[(long)k * lda];
        }
        if (BN == 128) {
            const float* Bp = B + (long)k0 * ldb + n0 + tid;
#pragma unroll
            for (int k = 0; k < 16; k++) pb[k] = Bp[(long)k * ldb];
        } else {
            const float* Bp = B + (long)(k0 + (tid >> 6) * 8) * ldb + n0 + (tid & 63);
#pragma unroll
            for (int k = 0; k < 8; k++) pb[k] = Bp[(long)k * ldb];
        }
    };

    auto storeTile = [&](int buf) {
#pragma unroll
        for (int g = 0; g < 4; g++) {
            uint4 u;
            u.x = f2tf32(pa[g * 4 + 0]); u.y = f2tf32(pa[g * 4 + 1]);
            u.z = f2tf32(pa[g * 4 + 2]); u.w = f2tf32(pa[g * 4 + 3]);
            *(uint4*)&As[buf][tid][g * 4] = u;
        }
        if (BN == 128) {
#pragma unroll
            for (int g = 0; g < 4; g++) {
                uint4 u;
                u.x = f2tf32(pb[g * 4 + 0]); u.y = f2tf32(pb[g * 4 + 1]);
                u.z = f2tf32(pb[g * 4 + 2]); u.w = f2tf32(pb[g * 4 + 3]);
                *(uint4*)&Bs[buf][tid][g * 4] = u;
            }
        } else {
            const int n = tid & 63, kg = (tid >> 6) * 8;
#pragma unroll
            for (int g = 0; g < 2; g++) {
                uint4 u;
                u.x = f2tf32(pb[g * 4 + 0]); u.y = f2tf32(pb[g * 4 + 1]);
                u.z = f2tf32(pb[g * 4 + 2]); u.w = f2tf32(pb[g * 4 + 3]);
                *(uint4*)&Bs[buf][n][kg + g * 4] = u;
            }
        }
    };

    auto computeTile = [&](int buf) {
#pragma unroll
        for (int ks = 0; ks < 16; ks += 8) {
            uint32_t af[4][4];
            uint32_t bf[NJ][2];
#pragma unroll
            for (int i = 0; i < 4; i++) {
                unsigned addr = asU + (unsigned)((buf * 128 * 20 +
                    (warpM * 64 + i * 16 + ldsmRow) * 20 + ks + ldsmK) * 4);
                LDSM4(af[i][0], af[i][1], af[i][2], af[i][3], addr);
            }
#pragma unroll
            for (int jj = 0; jj < NJJ; jj++) {
                unsigned addr = bsU + (unsigned)((buf * BN * 20 +
                    (warpN * WN + jj * 16 + ldsmRow) * 20 + ks + ldsmK) * 4);
                uint32_t r0, r1, r2, r3;
                LDSM4(r0, r1, r2, r3, addr);
                bf[jj * 2][0] = r0; bf[jj * 2 + 1][0] = r1;
                bf[jj * 2][1] = r2; bf[jj * 2 + 1][1] = r3;
            }
#pragma unroll
            for (int i = 0; i < 4; i++)
#pragma unroll
                for (int j = 0; j < NJ; j++)
                    MMA_TF32(acc[i][j], af[i], bf[j]);
        }
    };

    loadTile(0);
    storeTile(0);
    __syncthreads();
    for (int kt = 0; kt < ntiles; kt++) {
        const int buf = kt & 1;
        const bool more = (kt + 1) < ntiles;
        if (more) loadTile((kt + 1) << 4);
        computeTile(buf);
        if (more) storeTile(buf ^ 1);
        __syncthreads();
    }

    // ---- epilogue ----
    float vmax = -1e30f;
#pragma unroll
    for (int i = 0; i < 4; i++) {
        const int rL = m0 + warpM * 64 + i * 16 + gid;
        float dv0 = 1.f, dv1 = 1.f;
        if (rowdiv) { dv0 = 1.0f / rowdiv[rL]; dv1 = 1.0f / rowdiv[rL + 8]; }
#pragma unroll
        for (int j = 0; j < NJ; j++) {
            const int col = n0 + warpN * WN + (j >> 1) * 16 + (j & 1) * 8 + tig * 2;
            float v0 = alpha * acc[i][j][0], v1 = alpha * acc[i][j][1];
            float v2 = alpha * acc[i][j][2], v3 = alpha * acc[i][j][3];
            if (maxOut)
                vmax = fmaxf(vmax, fmaxf(fmaxf(v0, v1), fmaxf(v2, v3)));
            if (bias) {
                float2 bv = *(const float2*)(bias + col);
                v0 += bv.x; v1 += bv.y; v2 += bv.x; v3 += bv.y;
            }
            v0 *= dv0; v1 *= dv0; v2 *= dv1; v3 *= dv1;
            *(float2*)(C + (long)rL * ldc + col) = make_float2(v0, v1);
            *(float2*)(C + (long)(rL + 8) * ldc + col) = make_float2(v2, v3);
        }
    }

    if (maxOut) {
        vmax = warpRedMax(vmax);
        if (lane == 0) redMax[warp] = vmax;
        __syncthreads();
        if (tid == 0) {
            float m = fmaxf(fmaxf(redMax[0], redMax[1]), fmaxf(redMax[2], redMax[3]));
            atomicMax(maxOut + blockIdx.z, encodeF(m));
        }
    }
}

// -------------------- elementwise / reduction kernels ----------------------
__global__ void transpose_proj(const float* __restrict__ proj, float* __restrict__ projT) {
    int i = blockIdx.x * 256 + threadIdx.x;   // 16384
    int m = i >> 6, d = i & 63;
    projT[d * MF + m] = proj[i];
}

__global__ void init_stab(unsigned* __restrict__ s) {
    s[threadIdx.x] = 0u;   // minimum of the monotone float encoding
}

// phi_k fused with diag recompute + k_cumsum partials.
// grid (64 row-chunks, 64 bh), 256 threads; each thread owns one feature col.
__global__ __launch_bounds__(256) void phi_k_fused(
    const float* __restrict__ Km, float* __restrict__ kp,
    const unsigned* __restrict__ stabEnc, float* __restrict__ kcPart)
{
    __shared__ float diag[64];
    const int chunk = blockIdx.x, bh = blockIdx.y;
    const int b = bh >> 3, h = bh & 7;
    const int t = threadIdx.x;
    const int s0 = chunk * 64;

    {   // diag[r] = 0.5 * ||K_row||^2 * dn^2  (= ss * 0.0625)
        const int r = t >> 2, p = t & 3;
        const float* kr = Km + ((long)(b * NK + s0 + r)) * DMODEL + h * DHD + p * 16;
        float ss = 0.f;
#pragma unroll
        for (int i = 0; i < 4; i++) {
            float4 v = *(const float4*)(kr + i * 4);
            ss += v.x * v.x + v.y * v.y + v.z * v.z + v.w * v.w;
        }
        ss += __shfl_xor_sync(0xffffffffu, ss, 1);
        ss += __shfl_xor_sync(0xffffffffu, ss, 2);
        if (p == 0) diag[r] = ss * 0.0625f;
    }
    __syncthreads();

    const float stab = decodeF(stabEnc[bh]);
    float* kb = kp + ((long)bh * NK + s0) * MF;
    float csum = 0.f;
#pragma unroll 4
    for (int r = 0; r < 64; r++) {
        const long idx = (long)r * MF + t;
        float val = RATIO * (expf(kb[idx] - diag[r] - stab) + EPSF);
        kb[idx] = val;
        csum += val;
    }
    kcPart[((long)chunk * BHN + bh) * MF + t] = csum;
}

__global__ void kc_final(const float* __restrict__ part, float* __restrict__ kc) {
    int bh = blockIdx.x, t = threadIdx.x;
    float s = 0.f;
    for (int c = 0; c < 64; c++) s += part[((long)c * BHN + bh) * MF + t];
    kc[bh * MF + t] = s;
}

// phi_q fused with denominator (qp . kc). One block per (bh, n) row.
__global__ __launch_bounds__(256) void phi_q_fused(
    const float* __restrict__ Q, float* __restrict__ dq,
    const float* __restrict__ kc, float* __restrict__ denom)
{
    int r = blockIdx.x;       // 0..65535
    int t = threadIdx.x;      // 256
    int bh = r >> 10, n = r & 1023;
    int b = bh >> 3, h = bh & 7;
    float val = dq[(long)r * MF + t];
    float x = 0.f;
    if (t < DHD) x = Q[((long)(b * NQ + n)) * DMODEL + h * DHD + t];
    float ss = blockSum256(x * x);
    float mx = blockMax256(val);
    float qv = RATIO * (expf(val - ss * 0.0625f - mx) + EPSF);
    dq[(long)r * MF + t] = qv;
    float d = blockSum256(qv * kc[bh * MF + t]);
    if (t == 0) denom[r] = d;
}

__global__ void reduce_ctx(const float* __restrict__ p, float* __restrict__ c) {
    int i = blockIdx.x * 256 + threadIdx.x;   // 64*256*64 = 1048576 total
    c[i] = (p[i] + p[i + 1048576]) + (p[i + 2097152] + p[i + 3145728]);
}

// ---------------------------------------------------------------------------
extern "C" void kernel_launch(void* const* d_in, const int* in_sizes, int n_in,
                              void* d_out, int out_size)
{
    (void)in_sizes; (void)n_in; (void)out_size;
    const float* x       = (const float*)d_in[0];
    const float* context = (const float*)d_in[1];
    const float* Wq      = (const float*)d_in[2];
    const float* Wk      = (const float*)d_in[3];
    const float* Wv      = (const float*)d_in[4];
    const float* Wo      = (const float*)d_in[5];
    const float* bo      = (const float*)d_in[6];
    const float* proj    = (const float*)d_in[7];
    float* out = (float*)d_out;

    float *Q, *K, *V, *projT, *qp, *kp, *kcPart, *kc, *denom;
    float *ctxPart, *ctx, *attn;
    unsigned* stabEnc;
    cudaGetSymbolAddress((void**)&Q, g_Q);
    cudaGetSymbolAddress((void**)&K, g_K);
    cudaGetSymbolAddress((void**)&V, g_V);
    cudaGetSymbolAddress((void**)&projT, g_projT);
    cudaGetSymbolAddress((void**)&qp, g_qp);
    cudaGetSymbolAddress((void**)&kp, g_kp);
    cudaGetSymbolAddress((void**)&stabEnc, g_stabEnc);
    cudaGetSymbolAddress((void**)&kcPart, g_kcPart);
    cudaGetSymbolAddress((void**)&kc, g_kc);
    cudaGetSymbolAddress((void**)&denom, g_denom);
    cudaGetSymbolAddress((void**)&ctxPart, g_ctxPart);
    cudaGetSymbolAddress((void**)&ctx, g_ctx);
    cudaGetSymbolAddress((void**)&attn, g_attn);

    transpose_proj<<<64, 256>>>(proj, projT);
    init_stab<<<1, BHN>>>(stabEnc);

    // Q/K/V projections
    tmma2<128, false><<<dim3(4, 64, 1), 128>>>(x, Wq, Q, nullptr, nullptr, nullptr,
        DMODEL, DMODEL, DMODEL, DMODEL,
        1, 1, 0, 0, 0, 0, 0, 0, 0, 0, 0, 0, 0, 1.f);
    tmma2<128, false><<<dim3(4, 256, 1), 128>>>(context, Wk, K, nullptr, nullptr, nullptr,
        DMODEL, DMODEL, DMODEL, DMODEL,
        1, 1, 0, 0, 0, 0, 0, 0, 0, 0, 0, 0, 0, 1.f);
    tmma2<128, false><<<dim3(4, 256, 1), 128>>>(context, Wv, V, nullptr, nullptr, nullptr,
        DMODEL, DMODEL, DMODEL, DMODEL,
        1, 1, 0, 0, 0, 0, 0, 0, 0, 0, 0, 0, 0, 1.f);

    // dashQ[b,h,n,m] = dn * (Q_head @ projT),  z = b*8 + h
    tmma2<128, false><<<dim3(2, 8, BHN), 128>>>(Q, projT, qp, nullptr, nullptr, nullptr,
        DHD, DMODEL, MF, MF,
        8, 8,
        0, (long)NQ * DMODEL, DHD,
        0, 0, 0,
        0, (long)NH * NQ * MF, (long)NQ * MF,
        0, 0, DN_SCALE);

    // dashK[b,h,s,m] + fused global-max into stabEnc
    tmma2<128, false><<<dim3(2, 32, BHN), 128>>>(K, projT, kp, nullptr, nullptr, stabEnc,
        DHD, DMODEL, MF, MF,
        8, 8,
        0, (long)NK * DMODEL, DHD,
        0, 0, 0,
        0, (long)NH * NK * MF, (long)NK * MF,
        0, 0, DN_SCALE);

    // kp -> phi(kp), fused diag + k_cumsum partials
    phi_k_fused<<<dim3(64, 64), 256>>>(K, kp, stabEnc, kcPart);
    kc_final<<<BHN, 256>>>(kcPart, kc);

    // qp -> phi(qp), fused denominator
    phi_q_fused<<<BHN * NQ, 256>>>(Q, qp, kc, denom);

    // ctx = kp^T @ V, split-K=4:  z = (split*8 + b)*8 + h
    tmma2<64, true><<<dim3(1, 2, 256), 128>>>(kp, V, ctxPart, nullptr, nullptr, nullptr,
        1024, MF, DMODEL, DHD,
        8, 8,
        (long)1024 * MF, (long)NH * NK * MF, (long)NK * MF,
        (long)1024 * DMODEL, (long)NK * DMODEL, DHD,
        (long)BHN * MF * DHD, (long)NH * MF * DHD, (long)MF * DHD,
        0, 0, 1.f);
    reduce_ctx<<<4096, 256>>>(ctxPart, ctx);

    // attn = (qp @ ctx) / denom, written in merged-head layout.  z = b*8 + h
    tmma2<64, false><<<dim3(1, 8, BHN), 128>>>(qp, ctx, attn, nullptr, denom, nullptr,
        MF, MF, DHD, DMODEL,
        8, 8,
        0, (long)NH * NQ * MF, (long)NQ * MF,
        0, (long)NH * MF * DHD, (long)MF * DHD,
        0, (long)NQ * DMODEL, DHD,
        (long)NH * NQ, NQ, 1.f);

    // final projection + bias
    tmma2<128, false><<<dim3(4, 64, 1), 128>>>(attn, Wo, out, bo, nullptr, nullptr,
        DMODEL, DMODEL, DMODEL, DMODEL,
        1, 1, 0, 0, 0, 0, 0, 0, 0, 0, 0, 0, 0, 1.f);
}